// round 13
// baseline (speedup 1.0000x reference)
#include <cuda_runtime.h>
#include <cuda_bf16.h>
#include <cstdint>

// Problem constants
constexpr int NP = 4096;   // data_length
constexpr int KD = 8192;   // T_IN * D_IN
constexpr int FD = 2048;   // F
constexpr float GAMMA = 1.0f / 2048.0f;

constexpr int BK = 64;
constexpr int KSPLIT = 4;             // GEMM1 split-K factor
constexpr int KQ = KD / KSPLIT;       // 2048 per split
constexpr size_t NPFD = (size_t)NP * FD;

// Scratch (device globals; no runtime allocation)
__device__ __nv_bfloat16 g_xsb[(size_t)NP * KD];      // xs bf16 (64 MB)
__device__ __nv_bfloat16 g_Wt[(size_t)FD * KD];       // W^T bf16 (32 MB)
__device__ __nv_bfloat16 g_Xh[(size_t)KSPLIT * NPFD]; // split-K slabs bf16 (64 MB)
__device__ __nv_bfloat16 g_Xb[NPFD];                  // X bf16 (16 MB)
__device__ float g_sq[NP];
__device__ float g_bv[NP];
__device__ int g_cnt[256];  // per-output-tile arrival counters (GEMM1)

// ---------------------------------------------------------------------------
__device__ __forceinline__ uint32_t s2u(const void* p) {
    return (uint32_t)__cvta_generic_to_shared(p);
}
__device__ __forceinline__ uint32_t swz(uint32_t o) { return o ^ ((o >> 3) & 0x70); }
__device__ __forceinline__ void cpa16(uint32_t d, const void* g) {
    asm volatile("cp.async.cg.shared.global [%0], [%1], 16;\n" ::"r"(d), "l"(g));
}
__device__ __forceinline__ void cp_commit() {
    asm volatile("cp.async.commit_group;\n" ::: "memory");
}
__device__ __forceinline__ void ldmx4(uint32_t& r0, uint32_t& r1, uint32_t& r2,
                                      uint32_t& r3, uint32_t a) {
    asm volatile("ldmatrix.sync.aligned.m8n8.x4.shared.b16 {%0,%1,%2,%3}, [%4];\n"
                 : "=r"(r0), "=r"(r1), "=r"(r2), "=r"(r3) : "r"(a));
}
__device__ __forceinline__ void mma_bf16(float c[4], const uint32_t a[4],
                                         const uint32_t b[2]) {
    asm volatile(
        "mma.sync.aligned.m16n8k16.row.col.f32.bf16.bf16.f32 "
        "{%0,%1,%2,%3}, {%4,%5,%6,%7}, {%8,%9}, {%0,%1,%2,%3};\n"
        : "+f"(c[0]), "+f"(c[1]), "+f"(c[2]), "+f"(c[3])
        : "r"(a[0]), "r"(a[1]), "r"(a[2]), "r"(a[3]), "r"(b[0]), "r"(b[1]));
}

// Load one BK=64 stage: A[128 rows] + B[BNT rows], 128B swizzled rows.
template <int BNT, int NSTG>
__device__ __forceinline__ void load_stage(const __nv_bfloat16* A,
                                           const __nv_bfloat16* B, size_t ldA,
                                           size_t ldB, uint32_t sb, int kt) {
    constexpr int AST = 128 * 128;
    constexpr int STG = AST + BNT * 128;
    const int tid = threadIdx.x;
    const uint32_t sa = sb + (kt % NSTG) * STG;
    const uint32_t sbm = sa + AST;
    const __nv_bfloat16* As = A + (size_t)kt * BK;
    const __nv_bfloat16* Bs = B + (size_t)kt * BK;
#pragma unroll
    for (int t = 0; t < 4; t++) {
        int ch = tid + t * 256, r = ch >> 3, c = ch & 7;
        cpa16(sa + swz(r * 128 + c * 16), As + (size_t)r * ldA + c * 8);
    }
#pragma unroll
    for (int t = 0; t < BNT / 32; t++) {
        int ch = tid + t * 256, r = ch >> 3, c = ch & 7;
        cpa16(sbm + swz(r * 128 + c * 16), Bs + (size_t)r * ldB + c * 8);
    }
}

// NT GEMM mainloop, single-barrier multistage pipeline (R10 best config).
// A [m][k], B [n][k] row-major bf16. 256 threads, 8 warps (2m x 4n),
// warp tile 64 x (WNI*8). Accum c[4][WNI][4]. Frag double-buffered.
template <int BNT, int WNI, int NSTG>
__device__ __forceinline__ void gemm_mainloop(const __nv_bfloat16* __restrict__ A,
                                              const __nv_bfloat16* __restrict__ B,
                                              size_t ldA, size_t ldB, int kIters,
                                              float c[4][WNI][4]) {
    constexpr int AST = 128 * 128;
    constexpr int STG = AST + BNT * 128;
    extern __shared__ char smem[];
    const uint32_t sb = s2u(smem);
    const int tid = threadIdx.x, lane = tid & 31, warp = tid >> 5;
    const int wm = (warp >> 2) * 64, wn = (warp & 3) * (WNI * 8);
    const int ra = lane & 15, klo = lane >> 4;
    const int bm8 = lane >> 3;
    const int brow = (lane & 7) + (bm8 >> 1) * 8;
    const int bk = bm8 & 1;

    auto lda_frags = [&](uint32_t sA, uint32_t sB, int ks, uint32_t a[4][4],
                         uint32_t b[WNI][2]) {
#pragma unroll
        for (int mi = 0; mi < 4; ++mi) {
            uint32_t ad = sA + swz((wm + mi * 16 + ra) * 128 + (klo + 2 * ks) * 16);
            ldmx4(a[mi][0], a[mi][1], a[mi][2], a[mi][3], ad);
        }
#pragma unroll
        for (int p = 0; p < WNI / 2; ++p) {
            uint32_t ad = sB + swz((wn + p * 16 + brow) * 128 + (bk + 2 * ks) * 16);
            uint32_t r0, r1, r2, r3;
            ldmx4(r0, r1, r2, r3, ad);
            b[2 * p][0] = r0; b[2 * p][1] = r1;
            b[2 * p + 1][0] = r2; b[2 * p + 1][1] = r3;
        }
    };

    // Prologue: fill NSTG-1 stages (the last buffer is filled inside iter 0).
#pragma unroll
    for (int s = 0; s < NSTG - 1; s++) {
        load_stage<BNT, NSTG>(A, B, ldA, ldB, sb, s);
        cp_commit();
    }

    for (int kt = 0; kt < kIters; ++kt) {
        asm volatile("cp.async.wait_group %0;\n" ::"n"(NSTG - 2) : "memory");
        __syncthreads();
        // Load stage kt+NSTG-1 into buffer (kt-1)%NSTG: consumed in iter kt-1,
        // all warps are past it (barrier above). Overlaps this iter's MMAs.
        if (kt + NSTG - 1 < kIters)
            load_stage<BNT, NSTG>(A, B, ldA, ldB, sb, kt + NSTG - 1);
        cp_commit();  // constant group count

        const uint32_t sA = sb + (kt % NSTG) * STG;
        const uint32_t sB = sA + AST;
        uint32_t a[2][4][4], b[2][WNI][2];
        lda_frags(sA, sB, 0, a[0], b[0]);
#pragma unroll
        for (int ks = 0; ks < 4; ++ks) {
            const int cur = ks & 1;
            if (ks < 3) lda_frags(sA, sB, ks + 1, a[cur ^ 1], b[cur ^ 1]);
#pragma unroll
            for (int mi = 0; mi < 4; ++mi)
#pragma unroll
                for (int ni = 0; ni < WNI; ++ni)
                    mma_bf16(c[mi][ni], a[cur][mi], b[cur][ni]);
        }
    }
    __syncthreads();  // protect smem reuse by caller epilogues
}

// ---------------------------------------------------------------------------
// Fused pre-pass: W transpose, xs fp32->bf16 (ILP-4), bv + sq/cnt zero,
// out[0] = -sum(alphas).
constexpr int TW_BLK = (FD / 32) * (KD / 64);  // 8192
constexpr int CV_BLK = 2048;
constexpr int BV_BLK = 16;
constexpr int PRE_BLK = TW_BLK + CV_BLK + BV_BLK + 1;
__global__ void __launch_bounds__(256) k_pre(const float* __restrict__ xs,
                                             const float* __restrict__ W,
                                             const int* __restrict__ ys,
                                             const float* __restrict__ alphas,
                                             float* __restrict__ out) {
    const int bid = blockIdx.x;
    const int tid = threadIdx.x;
    if (bid < TW_BLK) {  // transpose 64(k) x 32(n) tile of W
        __shared__ float s[64][33];
        const int nb = (bid & 63) * 32, kb = (bid >> 6) * 64;
        const int tx = tid & 31, ty = tid >> 5;
#pragma unroll
        for (int r = 0; r < 64; r += 8)
            s[ty + r][tx] = W[(size_t)(kb + ty + r) * FD + nb + tx];
        __syncthreads();
#pragma unroll
        for (int rr = 0; rr < 4; rr++) {
            int n = ty + rr * 8;
            __nv_bfloat162 v = __floats2bfloat162_rn(s[2 * tx][n], s[2 * tx + 1][n]);
            *(__nv_bfloat162*)(g_Wt + (size_t)(nb + n) * KD + kb + 2 * tx) = v;
        }
    } else if (bid < TW_BLK + CV_BLK) {  // convert xs, 16 passes, unroll 4
        const size_t base = (size_t)(bid - TW_BLK) * 256 + tid;
        const size_t stride = (size_t)CV_BLK * 256;  // 524288
        __nv_bfloat162* o = (__nv_bfloat162*)g_xsb;
        const float4* in = (const float4*)xs;
#pragma unroll 4
        for (int it = 0; it < 16; it++) {
            size_t i = base + (size_t)it * stride;
            float4 v = in[i];
            o[2 * i] = __floats2bfloat162_rn(v.x, v.y);
            o[2 * i + 1] = __floats2bfloat162_rn(v.z, v.w);
        }
    } else if (bid < TW_BLK + CV_BLK + BV_BLK) {  // bv + zero sq + counters
        const int b = bid - TW_BLK - CV_BLK;
        const int i = b * 256 + tid;
        g_bv[i] = alphas[i] * (float)(2 * ys[i] - 1);
        g_sq[i] = 0.f;
        if (b == 0) g_cnt[tid] = 0;
    } else {  // out[0] = -sum(alphas)
        float s = 0.f;
        for (int t = tid; t < NP; t += 256) s += alphas[t];
#pragma unroll
        for (int o = 16; o > 0; o >>= 1) s += __shfl_xor_sync(0xffffffffu, s, o);
        __shared__ float red[8];
        if ((tid & 31) == 0) red[tid >> 5] = s;
        __syncthreads();
        if (tid == 0) {
            float t = 0.f;
            for (int q = 0; q < 8; q++) t += red[q];
            out[0] = -t;
        }
    }
}

// GEMM1 split-K with fused combine: each CTA stores its bf16 slab, bumps the
// tile counter; the LAST arriver sums all 4 slabs (own from regs, fixed
// z-order => deterministic), writes bf16 g_Xb, and accumulates row norms
// from the ROUNDED values (exact diagonal cancellation in GEMM2).
__global__ void __launch_bounds__(256, 1) k_gemm1() {
    float c[4][8][4];
#pragma unroll
    for (int i = 0; i < 4; i++)
#pragma unroll
        for (int j = 0; j < 8; j++)
#pragma unroll
            for (int k = 0; k < 4; k++) c[i][j][k] = 0.f;
    const int rowB = blockIdx.y * 128, colB = blockIdx.x * 256;
    const int myz = blockIdx.z;
    const size_t koff = (size_t)myz * KQ;
    gemm_mainloop<256, 8, 4>(g_xsb + (size_t)rowB * KD + koff,
                             g_Wt + (size_t)colB * KD + koff, KD, KD, KQ / BK, c);
    const int tid = threadIdx.x;
    const int lane = tid & 31, warp = tid >> 5;
    const int wm = (warp >> 2) * 64, wn = (warp & 3) * 64;

    // Store own slab
    __nv_bfloat16* slab = g_Xh + (size_t)myz * NPFD;
#pragma unroll
    for (int mi = 0; mi < 4; mi++) {
        const int r0 = rowB + wm + mi * 16 + (lane >> 2);
#pragma unroll
        for (int ni = 0; ni < 8; ni++) {
            const int c0 = colB + wn + ni * 8 + (lane & 3) * 2;
            *(__nv_bfloat162*)(slab + (size_t)r0 * FD + c0) =
                __floats2bfloat162_rn(c[mi][ni][0], c[mi][ni][1]);
            *(__nv_bfloat162*)(slab + (size_t)(r0 + 8) * FD + c0) =
                __floats2bfloat162_rn(c[mi][ni][2], c[mi][ni][3]);
        }
    }
    __threadfence();
    __syncthreads();
    __shared__ int s_last;
    if (tid == 0) {
        int old = atomicAdd(&g_cnt[blockIdx.y * 8 + blockIdx.x], 1);
        s_last = (old == KSPLIT - 1) ? 1 : 0;
    }
    __syncthreads();
    if (!s_last) return;
    __threadfence();  // acquire: other CTAs' slab stores now visible

    // Combine: sum slabs z=0..3 in fixed order (own z from regs).
#pragma unroll
    for (int mi = 0; mi < 4; mi++) {
        const int r0 = rowB + wm + mi * 16 + (lane >> 2);
        float ss0 = 0.f, ss1 = 0.f;
#pragma unroll
        for (int ni = 0; ni < 8; ni++) {
            const int c0 = colB + wn + ni * 8 + (lane & 3) * 2;
            float a0 = 0.f, a1 = 0.f, b0 = 0.f, b1 = 0.f;
#pragma unroll
            for (int z = 0; z < KSPLIT; z++) {
                float v0, v1, v2, v3;
                if (z == myz) {
                    v0 = c[mi][ni][0]; v1 = c[mi][ni][1];
                    v2 = c[mi][ni][2]; v3 = c[mi][ni][3];
                } else {
                    const __nv_bfloat16* sl = g_Xh + (size_t)z * NPFD;
                    float2 f0 = __bfloat1622float2(
                        *(const __nv_bfloat162*)(sl + (size_t)r0 * FD + c0));
                    float2 f1 = __bfloat1622float2(
                        *(const __nv_bfloat162*)(sl + (size_t)(r0 + 8) * FD + c0));
                    v0 = f0.x; v1 = f0.y; v2 = f1.x; v3 = f1.y;
                }
                a0 += v0; a1 += v1; b0 += v2; b1 += v3;
            }
            __nv_bfloat162 w0 = __floats2bfloat162_rn(a0, a1);
            __nv_bfloat162 w1 = __floats2bfloat162_rn(b0, b1);
            *(__nv_bfloat162*)(g_Xb + (size_t)r0 * FD + c0) = w0;
            *(__nv_bfloat162*)(g_Xb + (size_t)(r0 + 8) * FD + c0) = w1;
            float2 f0 = __bfloat1622float2(w0), f1 = __bfloat1622float2(w1);
            ss0 += f0.x * f0.x + f0.y * f0.y;
            ss1 += f1.x * f1.x + f1.y * f1.y;
        }
        // reduce across the 4 lanes sharing each row, then spread atomics
        ss0 += __shfl_xor_sync(0xffffffffu, ss0, 1);
        ss0 += __shfl_xor_sync(0xffffffffu, ss0, 2);
        ss1 += __shfl_xor_sync(0xffffffffu, ss1, 1);
        ss1 += __shfl_xor_sync(0xffffffffu, ss1, 2);
        if ((lane & 3) == 0) {
            atomicAdd(&g_sq[r0], ss0);
            atomicAdd(&g_sq[r0 + 8], ss1);
        }
    }
}

// GEMM2 fused: 128(M) x 256(N) tiles, triangle tj >= ti>>1 (272 CTAs);
// boundary tile (ti>>1 == tj) gets per-element weights. -> atomicAdd(out).
__global__ void __launch_bounds__(256, 1) k_gemm2(float* __restrict__ out) {
    int ti = 0, rem = blockIdx.x;
    while (rem >= 16 - (ti >> 1)) { rem -= 16 - (ti >> 1); ti++; }
    const int tj = (ti >> 1) + rem;
    float c[4][8][4];
#pragma unroll
    for (int i = 0; i < 4; i++)
#pragma unroll
        for (int j = 0; j < 8; j++)
#pragma unroll
            for (int k = 0; k < 4; k++) c[i][j][k] = 0.f;
    gemm_mainloop<256, 8, 4>(g_Xb + (size_t)ti * 128 * FD,
                             g_Xb + (size_t)tj * 256 * FD, FD, FD, FD / BK, c);
    const int lane = threadIdx.x & 31, warp = threadIdx.x >> 5;
    const int wm = (warp >> 2) * 64, wn = (warp & 3) * 64;
    const bool bnd = ((ti >> 1) == tj);
    float acc = 0.f;
#pragma unroll
    for (int mi = 0; mi < 4; mi++) {
        const int i0 = ti * 128 + wm + mi * 16 + (lane >> 2);
        const int i1 = i0 + 8;
        const float sqi0 = g_sq[i0], sqi1 = g_sq[i1];
        const float bi0 = g_bv[i0], bi1 = g_bv[i1];
#pragma unroll
        for (int ni = 0; ni < 8; ni++) {
            const int j0 = tj * 256 + wn + ni * 8 + (lane & 3) * 2;
            const int j1 = j0 + 1;
            const float sqj0 = g_sq[j0], sqj1 = g_sq[j1];
            const float bj0 = g_bv[j0], bj1 = g_bv[j1];
            float e00 = bi0 * bj0 * __expf(-GAMMA * fmaxf(sqi0 + sqj0 - 2.f * c[mi][ni][0], 0.f));
            float e01 = bi0 * bj1 * __expf(-GAMMA * fmaxf(sqi0 + sqj1 - 2.f * c[mi][ni][1], 0.f));
            float e10 = bi1 * bj0 * __expf(-GAMMA * fmaxf(sqi1 + sqj0 - 2.f * c[mi][ni][2], 0.f));
            float e11 = bi1 * bj1 * __expf(-GAMMA * fmaxf(sqi1 + sqj1 - 2.f * c[mi][ni][3], 0.f));
            if (bnd) {
                auto wgt = [](int j, int i) {
                    return (j > i) ? 2.f : ((j == i) ? 1.f : 0.f);
                };
                acc += wgt(j0, i0) * e00 + wgt(j1, i0) * e01 +
                       wgt(j0, i1) * e10 + wgt(j1, i1) * e11;
            } else {
                acc += 2.f * (e00 + e01 + e10 + e11);
            }
        }
    }
#pragma unroll
    for (int o = 16; o > 0; o >>= 1) acc += __shfl_xor_sync(0xffffffffu, acc, o);
    extern __shared__ char smem[];
    float* red = (float*)smem;
    if (lane == 0) red[warp] = acc;
    __syncthreads();
    if (threadIdx.x == 0) {
        float s = 0.f;
        for (int q = 0; q < 8; q++) s += red[q];
        atomicAdd(out, 0.5f * s);
    }
}

// ---------------------------------------------------------------------------
constexpr int SMEM_GG = 4 * (128 * 128 + 256 * 128);  // 192 KB
constexpr int G2_GRID = 272;  // sum over ti of (16 - ti/2)

extern "C" void kernel_launch(void* const* d_in, const int* in_sizes, int n_in,
                              void* d_out, int out_size) {
    (void)in_sizes; (void)n_in; (void)out_size;
    const float* xs = (const float*)d_in[0];
    const float* W = (const float*)d_in[1];
    const int* ys = (const int*)d_in[2];
    const float* alphas = (const float*)d_in[3];
    float* out = (float*)d_out;

    cudaFuncSetAttribute(k_gemm1, cudaFuncAttributeMaxDynamicSharedMemorySize,
                         SMEM_GG);
    cudaFuncSetAttribute(k_gemm2, cudaFuncAttributeMaxDynamicSharedMemorySize,
                         SMEM_GG);

    k_pre<<<PRE_BLK, 256>>>(xs, W, ys, alphas, out);
    k_gemm1<<<dim3(FD / 256, NP / 128, KSPLIT), 256, SMEM_GG>>>();
    k_gemm2<<<G2_GRID, 256, SMEM_GG>>>(out);
}

// round 14
// speedup vs baseline: 1.2114x; 1.2114x over previous
#include <cuda_runtime.h>
#include <cuda_bf16.h>
#include <cstdint>

// Problem constants
constexpr int NP = 4096;   // data_length
constexpr int KD = 8192;   // T_IN * D_IN
constexpr int FD = 2048;   // F
constexpr float GAMMA = 1.0f / 2048.0f;

constexpr int BK = 64;
constexpr int KSPLIT = 4;             // GEMM1 split-K factor
constexpr int KQ = KD / KSPLIT;       // 2048 per split
constexpr size_t NPFD = (size_t)NP * FD;

// Scratch (device globals; no runtime allocation)
__device__ __nv_bfloat16 g_xsb[(size_t)NP * KD];      // xs bf16 (64 MB)
__device__ __nv_bfloat16 g_Wt[(size_t)FD * KD];       // W^T bf16 (32 MB)
__device__ __nv_bfloat16 g_Xh[(size_t)KSPLIT * NPFD]; // split-K slabs bf16 (64 MB)
__device__ __nv_bfloat16 g_Xb[NPFD];                  // X bf16 (16 MB)
__device__ float g_sq[NP];
__device__ float g_bv[NP];

// ---------------------------------------------------------------------------
__device__ __forceinline__ uint32_t s2u(const void* p) {
    return (uint32_t)__cvta_generic_to_shared(p);
}
__device__ __forceinline__ uint32_t swz(uint32_t o) { return o ^ ((o >> 3) & 0x70); }
__device__ __forceinline__ void cpa16(uint32_t d, const void* g) {
    asm volatile("cp.async.cg.shared.global [%0], [%1], 16;\n" ::"r"(d), "l"(g));
}
__device__ __forceinline__ void cp_commit() {
    asm volatile("cp.async.commit_group;\n" ::: "memory");
}
__device__ __forceinline__ void ldmx4(uint32_t& r0, uint32_t& r1, uint32_t& r2,
                                      uint32_t& r3, uint32_t a) {
    asm volatile("ldmatrix.sync.aligned.m8n8.x4.shared.b16 {%0,%1,%2,%3}, [%4];\n"
                 : "=r"(r0), "=r"(r1), "=r"(r2), "=r"(r3) : "r"(a));
}
__device__ __forceinline__ void mma_bf16(float c[4], const uint32_t a[4],
                                         const uint32_t b[2]) {
    asm volatile(
        "mma.sync.aligned.m16n8k16.row.col.f32.bf16.bf16.f32 "
        "{%0,%1,%2,%3}, {%4,%5,%6,%7}, {%8,%9}, {%0,%1,%2,%3};\n"
        : "+f"(c[0]), "+f"(c[1]), "+f"(c[2]), "+f"(c[3])
        : "r"(a[0]), "r"(a[1]), "r"(a[2]), "r"(a[3]), "r"(b[0]), "r"(b[1]));
}

// Load one BK=64 stage: A[128 rows] + B[BNT rows], 128B swizzled rows.
template <int BNT, int NSTG>
__device__ __forceinline__ void load_stage(const __nv_bfloat16* A,
                                           const __nv_bfloat16* B, size_t ldA,
                                           size_t ldB, uint32_t sb, int kt) {
    constexpr int AST = 128 * 128;
    constexpr int STG = AST + BNT * 128;
    const int tid = threadIdx.x;
    const uint32_t sa = sb + (kt % NSTG) * STG;
    const uint32_t sbm = sa + AST;
    const __nv_bfloat16* As = A + (size_t)kt * BK;
    const __nv_bfloat16* Bs = B + (size_t)kt * BK;
#pragma unroll
    for (int t = 0; t < 4; t++) {
        int ch = tid + t * 256, r = ch >> 3, c = ch & 7;
        cpa16(sa + swz(r * 128 + c * 16), As + (size_t)r * ldA + c * 8);
    }
#pragma unroll
    for (int t = 0; t < BNT / 32; t++) {
        int ch = tid + t * 256, r = ch >> 3, c = ch & 7;
        cpa16(sbm + swz(r * 128 + c * 16), Bs + (size_t)r * ldB + c * 8);
    }
}

// NT GEMM mainloop, single-barrier multistage pipeline (best-known config).
// A [m][k], B [n][k] row-major bf16. 256 threads, 8 warps (2m x 4n),
// warp tile 64 x (WNI*8). Accum c[4][WNI][4]. Frag double-buffered.
template <int BNT, int WNI, int NSTG>
__device__ __forceinline__ void gemm_mainloop(const __nv_bfloat16* __restrict__ A,
                                              const __nv_bfloat16* __restrict__ B,
                                              size_t ldA, size_t ldB, int kIters,
                                              float c[4][WNI][4]) {
    constexpr int AST = 128 * 128;
    constexpr int STG = AST + BNT * 128;
    extern __shared__ char smem[];
    const uint32_t sb = s2u(smem);
    const int tid = threadIdx.x, lane = tid & 31, warp = tid >> 5;
    const int wm = (warp >> 2) * 64, wn = (warp & 3) * (WNI * 8);
    const int ra = lane & 15, klo = lane >> 4;
    const int bm8 = lane >> 3;
    const int brow = (lane & 7) + (bm8 >> 1) * 8;
    const int bk = bm8 & 1;

    auto lda_frags = [&](uint32_t sA, uint32_t sB, int ks, uint32_t a[4][4],
                         uint32_t b[WNI][2]) {
#pragma unroll
        for (int mi = 0; mi < 4; ++mi) {
            uint32_t ad = sA + swz((wm + mi * 16 + ra) * 128 + (klo + 2 * ks) * 16);
            ldmx4(a[mi][0], a[mi][1], a[mi][2], a[mi][3], ad);
        }
#pragma unroll
        for (int p = 0; p < WNI / 2; ++p) {
            uint32_t ad = sB + swz((wn + p * 16 + brow) * 128 + (bk + 2 * ks) * 16);
            uint32_t r0, r1, r2, r3;
            ldmx4(r0, r1, r2, r3, ad);
            b[2 * p][0] = r0; b[2 * p][1] = r1;
            b[2 * p + 1][0] = r2; b[2 * p + 1][1] = r3;
        }
    };

    // Prologue: fill NSTG-1 stages (the last buffer is filled inside iter 0).
#pragma unroll
    for (int s = 0; s < NSTG - 1; s++) {
        load_stage<BNT, NSTG>(A, B, ldA, ldB, sb, s);
        cp_commit();
    }

    for (int kt = 0; kt < kIters; ++kt) {
        asm volatile("cp.async.wait_group %0;\n" ::"n"(NSTG - 2) : "memory");
        __syncthreads();
        // Load stage kt+NSTG-1 into buffer (kt-1)%NSTG: consumed in iter kt-1,
        // all warps are past it (barrier above). Overlaps this iter's MMAs.
        if (kt + NSTG - 1 < kIters)
            load_stage<BNT, NSTG>(A, B, ldA, ldB, sb, kt + NSTG - 1);
        cp_commit();  // constant group count

        const uint32_t sA = sb + (kt % NSTG) * STG;
        const uint32_t sB = sA + AST;
        uint32_t a[2][4][4], b[2][WNI][2];
        lda_frags(sA, sB, 0, a[0], b[0]);
#pragma unroll
        for (int ks = 0; ks < 4; ++ks) {
            const int cur = ks & 1;
            if (ks < 3) lda_frags(sA, sB, ks + 1, a[cur ^ 1], b[cur ^ 1]);
#pragma unroll
            for (int mi = 0; mi < 4; ++mi)
#pragma unroll
                for (int ni = 0; ni < WNI; ++ni)
                    mma_bf16(c[mi][ni], a[cur][mi], b[cur][ni]);
        }
    }
    __syncthreads();  // protect smem reuse by caller epilogues
}

// ---------------------------------------------------------------------------
// Fused pre-pass: W transpose, xs fp32->bf16 (ILP-4), bv, out[0] = -sum(a).
constexpr int TW_BLK = (FD / 32) * (KD / 64);  // 8192
constexpr int CV_BLK = 2048;
constexpr int BV_BLK = 16;
constexpr int PRE_BLK = TW_BLK + CV_BLK + BV_BLK + 1;
__global__ void __launch_bounds__(256) k_pre(const float* __restrict__ xs,
                                             const float* __restrict__ W,
                                             const int* __restrict__ ys,
                                             const float* __restrict__ alphas,
                                             float* __restrict__ out) {
    const int bid = blockIdx.x;
    const int tid = threadIdx.x;
    if (bid < TW_BLK) {  // transpose 64(k) x 32(n) tile of W
        __shared__ float s[64][33];
        const int nb = (bid & 63) * 32, kb = (bid >> 6) * 64;
        const int tx = tid & 31, ty = tid >> 5;
#pragma unroll
        for (int r = 0; r < 64; r += 8)
            s[ty + r][tx] = W[(size_t)(kb + ty + r) * FD + nb + tx];
        __syncthreads();
#pragma unroll
        for (int rr = 0; rr < 4; rr++) {
            int n = ty + rr * 8;
            __nv_bfloat162 v = __floats2bfloat162_rn(s[2 * tx][n], s[2 * tx + 1][n]);
            *(__nv_bfloat162*)(g_Wt + (size_t)(nb + n) * KD + kb + 2 * tx) = v;
        }
    } else if (bid < TW_BLK + CV_BLK) {  // convert xs, 16 passes, unroll 4
        const size_t base = (size_t)(bid - TW_BLK) * 256 + tid;
        const size_t stride = (size_t)CV_BLK * 256;  // 524288
        __nv_bfloat162* o = (__nv_bfloat162*)g_xsb;
        const float4* in = (const float4*)xs;
#pragma unroll 4
        for (int it = 0; it < 16; it++) {
            size_t i = base + (size_t)it * stride;
            float4 v = in[i];
            o[2 * i] = __floats2bfloat162_rn(v.x, v.y);
            o[2 * i + 1] = __floats2bfloat162_rn(v.z, v.w);
        }
    } else if (bid < TW_BLK + CV_BLK + BV_BLK) {  // bv
        const int i = (bid - TW_BLK - CV_BLK) * 256 + tid;
        g_bv[i] = alphas[i] * (float)(2 * ys[i] - 1);
    } else {  // out[0] = -sum(alphas)
        float s = 0.f;
        for (int t = tid; t < NP; t += 256) s += alphas[t];
#pragma unroll
        for (int o = 16; o > 0; o >>= 1) s += __shfl_xor_sync(0xffffffffu, s, o);
        __shared__ float red[8];
        if ((tid & 31) == 0) red[tid >> 5] = s;
        __syncthreads();
        if (tid == 0) {
            float t = 0.f;
            for (int q = 0; q < 8; q++) t += red[q];
            out[0] = -t;
        }
    }
}

// GEMM1 split-K: slab z = xs[:, zKQ:(z+1)KQ] @ W[zKQ:(z+1)KQ, :], bf16 stores.
__global__ void __launch_bounds__(256, 1) k_gemm1() {
    float c[4][8][4];
#pragma unroll
    for (int i = 0; i < 4; i++)
#pragma unroll
        for (int j = 0; j < 8; j++)
#pragma unroll
            for (int k = 0; k < 4; k++) c[i][j][k] = 0.f;
    const int rowB = blockIdx.y * 128, colB = blockIdx.x * 256;
    const size_t koff = (size_t)blockIdx.z * KQ;
    gemm_mainloop<256, 8, 4>(g_xsb + (size_t)rowB * KD + koff,
                             g_Wt + (size_t)colB * KD + koff, KD, KD, KQ / BK, c);
    __nv_bfloat16* slab = g_Xh + (size_t)blockIdx.z * NPFD;
    const int lane = threadIdx.x & 31, warp = threadIdx.x >> 5;
    const int wm = (warp >> 2) * 64, wn = (warp & 3) * 64;
#pragma unroll
    for (int mi = 0; mi < 4; mi++) {
        const int r0 = rowB + wm + mi * 16 + (lane >> 2);
#pragma unroll
        for (int ni = 0; ni < 8; ni++) {
            const int c0 = colB + wn + ni * 8 + (lane & 3) * 2;
            *(__nv_bfloat162*)(slab + (size_t)r0 * FD + c0) =
                __floats2bfloat162_rn(c[mi][ni][0], c[mi][ni][1]);
            *(__nv_bfloat162*)(slab + (size_t)(r0 + 8) * FD + c0) =
                __floats2bfloat162_rn(c[mi][ni][2], c[mi][ni][3]);
        }
    }
}

// Combine: sum 4 bf16 slabs in fp32 -> bf16 g_Xb + row norms from ROUNDED
// values (exact diagonal cancellation in GEMM2). Warp per row.
__global__ void __launch_bounds__(256) k_combine() {
    const int row = blockIdx.x * 8 + (threadIdx.x >> 5);
    const int lane = threadIdx.x & 31;
    const uint2* s0 = (const uint2*)(g_Xh + (size_t)row * FD);
    const uint2* s1 = (const uint2*)(g_Xh + NPFD + (size_t)row * FD);
    const uint2* s2 = (const uint2*)(g_Xh + 2 * NPFD + (size_t)row * FD);
    const uint2* s3 = (const uint2*)(g_Xh + 3 * NPFD + (size_t)row * FD);
    uint2* dst = (uint2*)(g_Xb + (size_t)row * FD);
    float ss = 0.f;
#pragma unroll
    for (int it = 0; it < 16; it++) {
        const int idx = it * 32 + lane;
        uint2 u0 = s0[idx], u1 = s1[idx], u2 = s2[idx], u3 = s3[idx];
        const __nv_bfloat162* h0 = (const __nv_bfloat162*)&u0;
        const __nv_bfloat162* h1 = (const __nv_bfloat162*)&u1;
        const __nv_bfloat162* h2 = (const __nv_bfloat162*)&u2;
        const __nv_bfloat162* h3 = (const __nv_bfloat162*)&u3;
        uint2 w;
        __nv_bfloat162* hw = (__nv_bfloat162*)&w;
#pragma unroll
        for (int q = 0; q < 2; q++) {
            float2 f0 = __bfloat1622float2(h0[q]), f1 = __bfloat1622float2(h1[q]);
            float2 f2 = __bfloat1622float2(h2[q]), f3 = __bfloat1622float2(h3[q]);
            float vx = (f0.x + f1.x) + (f2.x + f3.x);
            float vy = (f0.y + f1.y) + (f2.y + f3.y);
            __nv_bfloat162 bb = __floats2bfloat162_rn(vx, vy);
            hw[q] = bb;
            float2 fb = __bfloat1622float2(bb);
            ss += fb.x * fb.x + fb.y * fb.y;
        }
        dst[idx] = w;
    }
#pragma unroll
    for (int o = 16; o > 0; o >>= 1) ss += __shfl_xor_sync(0xffffffffu, ss, o);
    if (lane == 0) g_sq[row] = ss;
}

// GEMM2 fused: 128(M) x 256(N) tiles, triangle tj >= ti>>1 (272 CTAs);
// boundary tile (ti>>1 == tj) gets per-element weights. -> atomicAdd(out).
__global__ void __launch_bounds__(256, 1) k_gemm2(float* __restrict__ out) {
    int ti = 0, rem = blockIdx.x;
    while (rem >= 16 - (ti >> 1)) { rem -= 16 - (ti >> 1); ti++; }
    const int tj = (ti >> 1) + rem;
    float c[4][8][4];
#pragma unroll
    for (int i = 0; i < 4; i++)
#pragma unroll
        for (int j = 0; j < 8; j++)
#pragma unroll
            for (int k = 0; k < 4; k++) c[i][j][k] = 0.f;
    gemm_mainloop<256, 8, 4>(g_Xb + (size_t)ti * 128 * FD,
                             g_Xb + (size_t)tj * 256 * FD, FD, FD, FD / BK, c);
    const int lane = threadIdx.x & 31, warp = threadIdx.x >> 5;
    const int wm = (warp >> 2) * 64, wn = (warp & 3) * 64;
    const bool bnd = ((ti >> 1) == tj);
    float acc = 0.f;
#pragma unroll
    for (int mi = 0; mi < 4; mi++) {
        const int i0 = ti * 128 + wm + mi * 16 + (lane >> 2);
        const int i1 = i0 + 8;
        const float sqi0 = g_sq[i0], sqi1 = g_sq[i1];
        const float bi0 = g_bv[i0], bi1 = g_bv[i1];
#pragma unroll
        for (int ni = 0; ni < 8; ni++) {
            const int j0 = tj * 256 + wn + ni * 8 + (lane & 3) * 2;
            const int j1 = j0 + 1;
            const float sqj0 = g_sq[j0], sqj1 = g_sq[j1];
            const float bj0 = g_bv[j0], bj1 = g_bv[j1];
            float e00 = bi0 * bj0 * __expf(-GAMMA * fmaxf(sqi0 + sqj0 - 2.f * c[mi][ni][0], 0.f));
            float e01 = bi0 * bj1 * __expf(-GAMMA * fmaxf(sqi0 + sqj1 - 2.f * c[mi][ni][1], 0.f));
            float e10 = bi1 * bj0 * __expf(-GAMMA * fmaxf(sqi1 + sqj0 - 2.f * c[mi][ni][2], 0.f));
            float e11 = bi1 * bj1 * __expf(-GAMMA * fmaxf(sqi1 + sqj1 - 2.f * c[mi][ni][3], 0.f));
            if (bnd) {
                auto wgt = [](int j, int i) {
                    return (j > i) ? 2.f : ((j == i) ? 1.f : 0.f);
                };
                acc += wgt(j0, i0) * e00 + wgt(j1, i0) * e01 +
                       wgt(j0, i1) * e10 + wgt(j1, i1) * e11;
            } else {
                acc += 2.f * (e00 + e01 + e10 + e11);
            }
        }
    }
#pragma unroll
    for (int o = 16; o > 0; o >>= 1) acc += __shfl_xor_sync(0xffffffffu, acc, o);
    extern __shared__ char smem[];
    float* red = (float*)smem;
    if (lane == 0) red[warp] = acc;
    __syncthreads();
    if (threadIdx.x == 0) {
        float s = 0.f;
        for (int q = 0; q < 8; q++) s += red[q];
        atomicAdd(out, 0.5f * s);
    }
}

// ---------------------------------------------------------------------------
constexpr int SMEM_GG = 4 * (128 * 128 + 256 * 128);  // 192 KB
constexpr int G2_GRID = 272;  // sum over ti of (16 - ti/2)

extern "C" void kernel_launch(void* const* d_in, const int* in_sizes, int n_in,
                              void* d_out, int out_size) {
    (void)in_sizes; (void)n_in; (void)out_size;
    const float* xs = (const float*)d_in[0];
    const float* W = (const float*)d_in[1];
    const int* ys = (const int*)d_in[2];
    const float* alphas = (const float*)d_in[3];
    float* out = (float*)d_out;

    cudaFuncSetAttribute(k_gemm1, cudaFuncAttributeMaxDynamicSharedMemorySize,
                         SMEM_GG);
    cudaFuncSetAttribute(k_gemm2, cudaFuncAttributeMaxDynamicSharedMemorySize,
                         SMEM_GG);

    k_pre<<<PRE_BLK, 256>>>(xs, W, ys, alphas, out);
    k_gemm1<<<dim3(FD / 256, NP / 128, KSPLIT), 256, SMEM_GG>>>();
    k_combine<<<NP / 8, 256>>>();
    k_gemm2<<<G2_GRID, 256, SMEM_GG>>>(out);
}

// round 17
// speedup vs baseline: 1.2176x; 1.0051x over previous
#include <cuda_runtime.h>
#include <cuda_bf16.h>
#include <cstdint>

// Problem constants
constexpr int NP = 4096;   // data_length
constexpr int KD = 8192;   // T_IN * D_IN
constexpr int FD = 2048;   // F
constexpr float GAMMA = 1.0f / 2048.0f;

constexpr int BK = 64;
constexpr int KSPLIT = 4;             // GEMM1 split-K factor
constexpr int KQ = KD / KSPLIT;       // 2048 per split
constexpr size_t NPFD = (size_t)NP * FD;

// Scratch (device globals; no runtime allocation)
__device__ __nv_bfloat16 g_xsb[(size_t)NP * KD];      // xs bf16 (64 MB)
__device__ __nv_bfloat16 g_Wt[(size_t)FD * KD];       // W^T bf16 (32 MB)
__device__ __nv_bfloat16 g_Xh[(size_t)KSPLIT * NPFD]; // split-K slabs bf16 (64 MB)
__device__ __nv_bfloat16 g_Xb[NPFD];                  // X bf16 (16 MB)
__device__ float g_sq[NP];
__device__ float g_bv[NP];

// ---------------------------------------------------------------------------
__device__ __forceinline__ uint32_t s2u(const void* p) {
    return (uint32_t)__cvta_generic_to_shared(p);
}
__device__ __forceinline__ uint32_t swz(uint32_t o) { return o ^ ((o >> 3) & 0x70); }
__device__ __forceinline__ void cpa16(uint32_t d, const void* g) {
    asm volatile("cp.async.cg.shared.global [%0], [%1], 16;\n" ::"r"(d), "l"(g));
}
__device__ __forceinline__ void cp_commit() {
    asm volatile("cp.async.commit_group;\n" ::: "memory");
}
__device__ __forceinline__ void ldmx4(uint32_t& r0, uint32_t& r1, uint32_t& r2,
                                      uint32_t& r3, uint32_t a) {
    asm volatile("ldmatrix.sync.aligned.m8n8.x4.shared.b16 {%0,%1,%2,%3}, [%4];\n"
                 : "=r"(r0), "=r"(r1), "=r"(r2), "=r"(r3) : "r"(a));
}
__device__ __forceinline__ void mma_bf16(float c[4], const uint32_t a[4],
                                         const uint32_t b[2]) {
    asm volatile(
        "mma.sync.aligned.m16n8k16.row.col.f32.bf16.bf16.f32 "
        "{%0,%1,%2,%3}, {%4,%5,%6,%7}, {%8,%9}, {%0,%1,%2,%3};\n"
        : "+f"(c[0]), "+f"(c[1]), "+f"(c[2]), "+f"(c[3])
        : "r"(a[0]), "r"(a[1]), "r"(a[2]), "r"(a[3]), "r"(b[0]), "r"(b[1]));
}

// Load one BK=64 stage: A[128 rows] + B[BNT rows], 128B swizzled rows.
template <int BNT, int NSTG>
__device__ __forceinline__ void load_stage(const __nv_bfloat16* A,
                                           const __nv_bfloat16* B, size_t ldA,
                                           size_t ldB, uint32_t sb, int kt) {
    constexpr int AST = 128 * 128;
    constexpr int STG = AST + BNT * 128;
    const int tid = threadIdx.x;
    const uint32_t sa = sb + (kt % NSTG) * STG;
    const uint32_t sbm = sa + AST;
    const __nv_bfloat16* As = A + (size_t)kt * BK;
    const __nv_bfloat16* Bs = B + (size_t)kt * BK;
#pragma unroll
    for (int t = 0; t < 4; t++) {
        int ch = tid + t * 256, r = ch >> 3, c = ch & 7;
        cpa16(sa + swz(r * 128 + c * 16), As + (size_t)r * ldA + c * 8);
    }
#pragma unroll
    for (int t = 0; t < BNT / 32; t++) {
        int ch = tid + t * 256, r = ch >> 3, c = ch & 7;
        cpa16(sbm + swz(r * 128 + c * 16), Bs + (size_t)r * ldB + c * 8);
    }
}

// NT GEMM mainloop, single-barrier multistage pipeline (best-known config).
// A [m][k], B [n][k] row-major bf16. 256 threads, 8 warps (2m x 4n),
// warp tile 64 x (WNI*8). Accum c[4][WNI][4]. DB = frag double-buffering.
template <int BNT, int WNI, int NSTG, bool DB>
__device__ __forceinline__ void gemm_mainloop(const __nv_bfloat16* __restrict__ A,
                                              const __nv_bfloat16* __restrict__ B,
                                              size_t ldA, size_t ldB, int kIters,
                                              float c[4][WNI][4]) {
    constexpr int AST = 128 * 128;
    constexpr int STG = AST + BNT * 128;
    extern __shared__ char smem[];
    const uint32_t sb = s2u(smem);
    const int tid = threadIdx.x, lane = tid & 31, warp = tid >> 5;
    const int wm = (warp >> 2) * 64, wn = (warp & 3) * (WNI * 8);
    const int ra = lane & 15, klo = lane >> 4;
    const int bm8 = lane >> 3;
    const int brow = (lane & 7) + (bm8 >> 1) * 8;
    const int bk = bm8 & 1;

    auto lda_frags = [&](uint32_t sA, uint32_t sB, int ks, uint32_t a[4][4],
                         uint32_t b[WNI][2]) {
#pragma unroll
        for (int mi = 0; mi < 4; ++mi) {
            uint32_t ad = sA + swz((wm + mi * 16 + ra) * 128 + (klo + 2 * ks) * 16);
            ldmx4(a[mi][0], a[mi][1], a[mi][2], a[mi][3], ad);
        }
#pragma unroll
        for (int p = 0; p < WNI / 2; ++p) {
            uint32_t ad = sB + swz((wn + p * 16 + brow) * 128 + (bk + 2 * ks) * 16);
            uint32_t r0, r1, r2, r3;
            ldmx4(r0, r1, r2, r3, ad);
            b[2 * p][0] = r0; b[2 * p][1] = r1;
            b[2 * p + 1][0] = r2; b[2 * p + 1][1] = r3;
        }
    };

    // Prologue: fill NSTG-1 stages (the last buffer is filled inside iter 0).
#pragma unroll
    for (int s = 0; s < NSTG - 1; s++) {
        load_stage<BNT, NSTG>(A, B, ldA, ldB, sb, s);
        cp_commit();
    }

    for (int kt = 0; kt < kIters; ++kt) {
        asm volatile("cp.async.wait_group %0;\n" ::"n"(NSTG - 2) : "memory");
        __syncthreads();
        // Load stage kt+NSTG-1 into buffer (kt-1)%NSTG: consumed in iter kt-1,
        // all warps are past it (barrier above). Overlaps this iter's MMAs.
        if (kt + NSTG - 1 < kIters)
            load_stage<BNT, NSTG>(A, B, ldA, ldB, sb, kt + NSTG - 1);
        cp_commit();  // constant group count

        const uint32_t sA = sb + (kt % NSTG) * STG;
        const uint32_t sB = sA + AST;
        if (DB) {
            uint32_t a[2][4][4], b[2][WNI][2];
            lda_frags(sA, sB, 0, a[0], b[0]);
#pragma unroll
            for (int ks = 0; ks < 4; ++ks) {
                const int cur = ks & 1;
                if (ks < 3) lda_frags(sA, sB, ks + 1, a[cur ^ 1], b[cur ^ 1]);
#pragma unroll
                for (int mi = 0; mi < 4; ++mi)
#pragma unroll
                    for (int ni = 0; ni < WNI; ++ni)
                        mma_bf16(c[mi][ni], a[cur][mi], b[cur][ni]);
            }
        } else {
#pragma unroll
            for (int ks = 0; ks < 4; ++ks) {
                uint32_t a[4][4], b[WNI][2];
                lda_frags(sA, sB, ks, a, b);
#pragma unroll
                for (int mi = 0; mi < 4; ++mi)
#pragma unroll
                    for (int ni = 0; ni < WNI; ++ni)
                        mma_bf16(c[mi][ni], a[mi], b[ni]);
            }
        }
    }
    __syncthreads();  // protect smem reuse by caller epilogues
}

// ---------------------------------------------------------------------------
// Fused pre-pass: W transpose, xs fp32->bf16 (ILP-4), bv, out[0] = -sum(a).
constexpr int TW_BLK = (FD / 32) * (KD / 64);  // 8192
constexpr int CV_BLK = 2048;
constexpr int BV_BLK = 16;
constexpr int PRE_BLK = TW_BLK + CV_BLK + BV_BLK + 1;
__global__ void __launch_bounds__(256) k_pre(const float* __restrict__ xs,
                                             const float* __restrict__ W,
                                             const int* __restrict__ ys,
                                             const float* __restrict__ alphas,
                                             float* __restrict__ out) {
    const int bid = blockIdx.x;
    const int tid = threadIdx.x;
    if (bid < TW_BLK) {  // transpose 64(k) x 32(n) tile of W
        __shared__ float s[64][33];
        const int nb = (bid & 63) * 32, kb = (bid >> 6) * 64;
        const int tx = tid & 31, ty = tid >> 5;
#pragma unroll
        for (int r = 0; r < 64; r += 8)
            s[ty + r][tx] = W[(size_t)(kb + ty + r) * FD + nb + tx];
        __syncthreads();
#pragma unroll
        for (int rr = 0; rr < 4; rr++) {
            int n = ty + rr * 8;
            __nv_bfloat162 v = __floats2bfloat162_rn(s[2 * tx][n], s[2 * tx + 1][n]);
            *(__nv_bfloat162*)(g_Wt + (size_t)(nb + n) * KD + kb + 2 * tx) = v;
        }
    } else if (bid < TW_BLK + CV_BLK) {  // convert xs, 16 passes, unroll 4
        const size_t base = (size_t)(bid - TW_BLK) * 256 + tid;
        const size_t stride = (size_t)CV_BLK * 256;  // 524288
        __nv_bfloat162* o = (__nv_bfloat162*)g_xsb;
        const float4* in = (const float4*)xs;
#pragma unroll 4
        for (int it = 0; it < 16; it++) {
            size_t i = base + (size_t)it * stride;
            float4 v = in[i];
            o[2 * i] = __floats2bfloat162_rn(v.x, v.y);
            o[2 * i + 1] = __floats2bfloat162_rn(v.z, v.w);
        }
    } else if (bid < TW_BLK + CV_BLK + BV_BLK) {  // bv
        const int i = (bid - TW_BLK - CV_BLK) * 256 + tid;
        g_bv[i] = alphas[i] * (float)(2 * ys[i] - 1);
    } else {  // out[0] = -sum(alphas)
        float s = 0.f;
        for (int t = tid; t < NP; t += 256) s += alphas[t];
#pragma unroll
        for (int o = 16; o > 0; o >>= 1) s += __shfl_xor_sync(0xffffffffu, s, o);
        __shared__ float red[8];
        if ((tid & 31) == 0) red[tid >> 5] = s;
        __syncthreads();
        if (tid == 0) {
            float t = 0.f;
            for (int q = 0; q < 8; q++) t += red[q];
            out[0] = -t;
        }
    }
}

// GEMM1 split-K: slab z = xs[:, zKQ:(z+1)KQ] @ W[zKQ:(z+1)KQ, :], bf16 stores.
__global__ void __launch_bounds__(256, 1) k_gemm1() {
    float c[4][8][4];
#pragma unroll
    for (int i = 0; i < 4; i++)
#pragma unroll
        for (int j = 0; j < 8; j++)
#pragma unroll
            for (int k = 0; k < 4; k++) c[i][j][k] = 0.f;
    const int rowB = blockIdx.y * 128, colB = blockIdx.x * 256;
    const size_t koff = (size_t)blockIdx.z * KQ;
    gemm_mainloop<256, 8, 4, true>(g_xsb + (size_t)rowB * KD + koff,
                                   g_Wt + (size_t)colB * KD + koff, KD, KD,
                                   KQ / BK, c);
    __nv_bfloat16* slab = g_Xh + (size_t)blockIdx.z * NPFD;
    const int lane = threadIdx.x & 31, warp = threadIdx.x >> 5;
    const int wm = (warp >> 2) * 64, wn = (warp & 3) * 64;
#pragma unroll
    for (int mi = 0; mi < 4; mi++) {
        const int r0 = rowB + wm + mi * 16 + (lane >> 2);
#pragma unroll
        for (int ni = 0; ni < 8; ni++) {
            const int c0 = colB + wn + ni * 8 + (lane & 3) * 2;
            *(__nv_bfloat162*)(slab + (size_t)r0 * FD + c0) =
                __floats2bfloat162_rn(c[mi][ni][0], c[mi][ni][1]);
            *(__nv_bfloat162*)(slab + (size_t)(r0 + 8) * FD + c0) =
                __floats2bfloat162_rn(c[mi][ni][2], c[mi][ni][3]);
        }
    }
}

// Combine: sum 4 bf16 slabs in fp32 -> bf16 g_Xb + row norms from ROUNDED
// values (exact diagonal cancellation in GEMM2). Warp per row.
__global__ void __launch_bounds__(256) k_combine() {
    const int row = blockIdx.x * 8 + (threadIdx.x >> 5);
    const int lane = threadIdx.x & 31;
    const uint2* s0 = (const uint2*)(g_Xh + (size_t)row * FD);
    const uint2* s1 = (const uint2*)(g_Xh + NPFD + (size_t)row * FD);
    const uint2* s2 = (const uint2*)(g_Xh + 2 * NPFD + (size_t)row * FD);
    const uint2* s3 = (const uint2*)(g_Xh + 3 * NPFD + (size_t)row * FD);
    uint2* dst = (uint2*)(g_Xb + (size_t)row * FD);
    float ss = 0.f;
#pragma unroll
    for (int it = 0; it < 16; it++) {
        const int idx = it * 32 + lane;
        uint2 u0 = s0[idx], u1 = s1[idx], u2 = s2[idx], u3 = s3[idx];
        const __nv_bfloat162* h0 = (const __nv_bfloat162*)&u0;
        const __nv_bfloat162* h1 = (const __nv_bfloat162*)&u1;
        const __nv_bfloat162* h2 = (const __nv_bfloat162*)&u2;
        const __nv_bfloat162* h3 = (const __nv_bfloat162*)&u3;
        uint2 w;
        __nv_bfloat162* hw = (__nv_bfloat162*)&w;
#pragma unroll
        for (int q = 0; q < 2; q++) {
            float2 f0 = __bfloat1622float2(h0[q]), f1 = __bfloat1622float2(h1[q]);
            float2 f2 = __bfloat1622float2(h2[q]), f3 = __bfloat1622float2(h3[q]);
            float vx = (f0.x + f1.x) + (f2.x + f3.x);
            float vy = (f0.y + f1.y) + (f2.y + f3.y);
            __nv_bfloat162 bb = __floats2bfloat162_rn(vx, vy);
            hw[q] = bb;
            float2 fb = __bfloat1622float2(bb);
            ss += fb.x * fb.x + fb.y * fb.y;
        }
        dst[idx] = w;
    }
#pragma unroll
    for (int o = 16; o > 0; o >>= 1) ss += __shfl_xor_sync(0xffffffffu, ss, o);
    if (lane == 0) g_sq[row] = ss;
}

// GEMM2 fused (best-measured config: 128x128 tiles, occ-2, packed exact
// triangle): S = X_i @ X_j^T, then sum b_i b_j exp(-gamma*d2); off-diagonal
// tiles x2; result atomically accumulated into out[0] (= -sum(alpha)).
__global__ void __launch_bounds__(256, 2) k_gemm2(float* __restrict__ out) {
    int ti = 0, rem = blockIdx.x;
    while (rem >= 32 - ti) { rem -= 32 - ti; ti++; }
    const int tj = ti + rem;
    float c[4][4][4];
#pragma unroll
    for (int i = 0; i < 4; i++)
#pragma unroll
        for (int j = 0; j < 4; j++)
#pragma unroll
            for (int k = 0; k < 4; k++) c[i][j][k] = 0.f;
    gemm_mainloop<128, 4, 3, false>(g_Xb + (size_t)ti * 128 * FD,
                                    g_Xb + (size_t)tj * 128 * FD, FD, FD,
                                    FD / BK, c);
    const int lane = threadIdx.x & 31, warp = threadIdx.x >> 5;
    const int wm = (warp >> 2) * 64, wn = (warp & 3) * 32;
    float acc = 0.f;
#pragma unroll
    for (int mi = 0; mi < 4; mi++) {
        const int i0 = ti * 128 + wm + mi * 16 + (lane >> 2);
        const int i1 = i0 + 8;
        const float sqi0 = g_sq[i0], sqi1 = g_sq[i1];
        const float bi0 = g_bv[i0], bi1 = g_bv[i1];
#pragma unroll
        for (int ni = 0; ni < 4; ni++) {
            const int j0 = tj * 128 + wn + ni * 8 + (lane & 3) * 2;
            const int j1 = j0 + 1;
            const float sqj0 = g_sq[j0], sqj1 = g_sq[j1];
            const float bj0 = g_bv[j0], bj1 = g_bv[j1];
            acc += bi0 * bj0 * __expf(-GAMMA * fmaxf(sqi0 + sqj0 - 2.f * c[mi][ni][0], 0.f));
            acc += bi0 * bj1 * __expf(-GAMMA * fmaxf(sqi0 + sqj1 - 2.f * c[mi][ni][1], 0.f));
            acc += bi1 * bj0 * __expf(-GAMMA * fmaxf(sqi1 + sqj0 - 2.f * c[mi][ni][2], 0.f));
            acc += bi1 * bj1 * __expf(-GAMMA * fmaxf(sqi1 + sqj1 - 2.f * c[mi][ni][3], 0.f));
        }
    }
    if (ti != tj) acc *= 2.f;
#pragma unroll
    for (int o = 16; o > 0; o >>= 1) acc += __shfl_xor_sync(0xffffffffu, acc, o);
    extern __shared__ char smem[];
    float* red = (float*)smem;
    if (lane == 0) red[warp] = acc;
    __syncthreads();
    if (threadIdx.x == 0) {
        float s = 0.f;
        for (int q = 0; q < 8; q++) s += red[q];
        atomicAdd(out, 0.5f * s);
    }
}

// ---------------------------------------------------------------------------
constexpr int SMEM_G1 = 4 * (128 * 128 + 256 * 128);  // 192 KB
constexpr int SMEM_G2 = 3 * (128 * 128 + 128 * 128);  // 96 KB

extern "C" void kernel_launch(void* const* d_in, const int* in_sizes, int n_in,
                              void* d_out, int out_size) {
    (void)in_sizes; (void)n_in; (void)out_size;
    const float* xs = (const float*)d_in[0];
    const float* W = (const float*)d_in[1];
    const int* ys = (const int*)d_in[2];
    const float* alphas = (const float*)d_in[3];
    float* out = (float*)d_out;

    cudaFuncSetAttribute(k_gemm1, cudaFuncAttributeMaxDynamicSharedMemorySize,
                         SMEM_G1);
    cudaFuncSetAttribute(k_gemm2, cudaFuncAttributeMaxDynamicSharedMemorySize,
                         SMEM_G2);

    k_pre<<<PRE_BLK, 256>>>(xs, W, ys, alphas, out);
    k_gemm1<<<dim3(FD / 256, NP / 128, KSPLIT), 256, SMEM_G1>>>();
    k_combine<<<NP / 8, 256>>>();
    k_gemm2<<<(32 * 33) / 2, 256, SMEM_G2>>>(out);
}